// round 5
// baseline (speedup 1.0000x reference)
#include <cuda_runtime.h>
#include <cuda_bf16.h>
#include <math.h>

#define Bsz  2
#define Tlen 512
#define Cdim 1024
#define Hn   16
#define Dd   64
#define CSz  64
#define NCH  8
#define KCV  4

// ---------------- scratch (static device globals; no allocation) ----------------
__device__ float g_xq[Bsz*Tlen*Cdim];
__device__ float g_xk[Bsz*Tlen*Cdim];
__device__ float g_xv[Bsz*Tlen*Cdim];
__device__ float g_q [Bsz*Tlen*Cdim];
__device__ float g_k [Bsz*Tlen*Cdim];
__device__ float g_v [Bsz*Tlen*Cdim];
__device__ float g_alpha[Bsz*Tlen*Hn];
__device__ float g_eta  [Bsz*Tlen*Hn];
__device__ float g_theta[Bsz*Tlen*Hn];
__device__ float g_gamma[Bsz*Tlen*Hn];
__device__ float g_M[Bsz*Hn*Dd*Dd];
__device__ float g_S[Bsz*Hn*Dd*Dd];
__device__ float g_chunkS[(size_t)Bsz*CSz*Hn*Dd*Dd];   // 33.5 MB
__device__ float g_y [Bsz*Tlen*Cdim];
__device__ float g_yn[Bsz*Tlen*Cdim];

__constant__ float PEC[5][3] = {
    {8.28721201814563f, -23.595886519098837f, 17.300387312530933f},
    {4.107059111542203f, -2.9478499167379106f, 0.5448431082926601f},
    {3.9486908534822946f, -2.908902115962949f, 0.5518191394370137f},
    {3.3184196573706015f, -2.488488024314874f, 0.51004894012372f},
    {2.300652019954817f, -1.6689039845747493f, 0.4188073119525673f},
};

// ---------------- zero persistent state ----------------
__global__ void zero_state_kernel() {
    int i = blockIdx.x * blockDim.x + threadIdx.x;
    if (i < Bsz*Hn*Dd*Dd) { g_M[i] = 0.f; g_S[i] = 0.f; }
}

// ---------------- SGEMM NT: C[m,n] = sum_k A[m,k]*B[n,k] ----------------
// Two-level accumulation: 16-term tile accumulator + Kahan fold into master.
__global__ __launch_bounds__(256) void sgemm_nt(
    const float* __restrict__ A, const float* __restrict__ B, float* __restrict__ C,
    int M, int N, int K)
{
    __shared__ float As[64][17];
    __shared__ float Bs[64][17];
    int tx = threadIdx.x & 15, ty = threadIdx.x >> 4;
    int m0 = blockIdx.y * 64, n0 = blockIdx.x * 64;
    float acc[4][4] = {};
    float cmp[4][4] = {};
    for (int k0 = 0; k0 < K; k0 += 16) {
        #pragma unroll
        for (int i = 0; i < 4; i++) {
            int e = threadIdx.x + 256*i;
            int r = e >> 4, kk = e & 15;
            As[r][kk] = A[(size_t)(m0+r)*K + k0 + kk];
            Bs[r][kk] = B[(size_t)(n0+r)*K + k0 + kk];
        }
        __syncthreads();
        float tacc[4][4] = {};
        #pragma unroll
        for (int kk = 0; kk < 16; kk++) {
            float ar[4], br[4];
            #pragma unroll
            for (int r = 0; r < 4; r++) ar[r] = As[ty*4+r][kk];
            #pragma unroll
            for (int c = 0; c < 4; c++) br[c] = Bs[tx*4+c][kk];
            #pragma unroll
            for (int r = 0; r < 4; r++)
                #pragma unroll
                for (int c = 0; c < 4; c++)
                    tacc[r][c] += ar[r]*br[c];
        }
        // Kahan fold tile accumulator into master
        #pragma unroll
        for (int r = 0; r < 4; r++)
            #pragma unroll
            for (int c = 0; c < 4; c++) {
                float y = tacc[r][c] - cmp[r][c];
                float s = acc[r][c] + y;
                cmp[r][c] = (s - acc[r][c]) - y;
                acc[r][c] = s;
            }
        __syncthreads();
    }
    #pragma unroll
    for (int r = 0; r < 4; r++)
        #pragma unroll
        for (int c = 0; c < 4; c++)
            C[(size_t)(m0+ty*4+r)*N + n0 + tx*4 + c] = acc[r][c] - cmp[r][c];
}

// ---------------- causal depthwise conv (+ optional rmsnorm+poly per head) ----------------
__global__ __launch_bounds__(256) void conv_feat_kernel(
    const float* __restrict__ xin, const float* __restrict__ w,
    const float* __restrict__ bias, float* __restrict__ outp, int do_norm)
{
    int bt = blockIdx.x;
    int b = bt / Tlen, t = bt % Tlen;
    int c0 = threadIdx.x * 4;
    float val[4];
    #pragma unroll
    for (int u = 0; u < 4; u++) {
        int c = c0 + u;
        float acc = bias[c];
        #pragma unroll
        for (int j = 0; j < KCV; j++) {
            int tt = t - (KCV-1) + j;
            if (tt >= 0) acc += w[c*KCV + j] * xin[(size_t)(b*Tlen + tt)*Cdim + c];
        }
        val[u] = acc;
    }
    if (do_norm) {
        float ss = val[0]*val[0] + val[1]*val[1] + val[2]*val[2] + val[3]*val[3];
        #pragma unroll
        for (int m = 1; m < 16; m <<= 1) ss += __shfl_xor_sync(0xffffffffu, ss, m);
        float r = rsqrtf(ss * (1.f/64.f) + 1e-6f);
        #pragma unroll
        for (int u = 0; u < 4; u++) {
            float xn = val[u] * r;
            val[u] = xn + 0.5f*xn*xn;
        }
    }
    float4* o4 = (float4*)(outp + (size_t)bt*Cdim + c0);
    *o4 = make_float4(val[0], val[1], val[2], val[3]);
}

// ---------------- final per-head rmsnorm of y ----------------
__global__ __launch_bounds__(256) void ynorm_kernel(
    const float* __restrict__ yin, float* __restrict__ outp)
{
    int bt = blockIdx.x;
    int c0 = threadIdx.x * 4;
    float val[4];
    #pragma unroll
    for (int u = 0; u < 4; u++) val[u] = yin[(size_t)bt*Cdim + c0 + u];
    float ss = val[0]*val[0] + val[1]*val[1] + val[2]*val[2] + val[3]*val[3];
    #pragma unroll
    for (int m = 1; m < 16; m <<= 1) ss += __shfl_xor_sync(0xffffffffu, ss, m);
    float r = rsqrtf(ss * (1.f/64.f) + 1e-6f);
    float4* o4 = (float4*)(outp + (size_t)bt*Cdim + c0);
    *o4 = make_float4(val[0]*r, val[1]*r, val[2]*r, val[3]*r);
}

// ---------------- gates: sigmoid(x @ W.T) for 4 weight matrices ----------------
// 4 independent 64-term chains + tree sum (accuracy: amplified via scans).
__global__ __launch_bounds__(256) void gates_kernel(
    const float* __restrict__ x,
    const float* __restrict__ Wa, const float* __restrict__ We,
    const float* __restrict__ Wt, const float* __restrict__ Wg)
{
    __shared__ float xs[Cdim];
    int bt = blockIdx.x;
    int tid = threadIdx.x;
    #pragma unroll
    for (int i = 0; i < 4; i++) xs[tid + 256*i] = x[(size_t)bt*Cdim + tid + 256*i];
    __syncthreads();
    int oi = tid >> 2, part = tid & 3;
    int mat = oi >> 4, h = oi & 15;
    const float* W = (mat==0) ? Wa : (mat==1) ? We : (mat==2) ? Wt : Wg;
    W += h*Cdim + part*256;
    const float* xp = xs + part*256;
    float a0 = 0.f, a1 = 0.f, a2 = 0.f, a3 = 0.f;
    #pragma unroll 8
    for (int i = 0; i < 64; i++) {
        a0 += xp[i]      * W[i];
        a1 += xp[64+i]   * W[64+i];
        a2 += xp[128+i]  * W[128+i];
        a3 += xp[192+i]  * W[192+i];
    }
    float acc = (a0 + a1) + (a2 + a3);
    acc += __shfl_xor_sync(0xffffffffu, acc, 1);
    acc += __shfl_xor_sync(0xffffffffu, acc, 2);
    if (part == 0) {
        float s = 1.f/(1.f + expf(-acc));
        float* out = (mat==0) ? g_alpha : (mat==1) ? g_eta : (mat==2) ? g_theta : g_gamma;
        out[bt*Hn + h] = s;
    }
}

// ---------------- per-chunk: err, omega window, momentum scan -> g_chunkS ----------------
#define CE_SMEM ((64*65 + 64*64*2)*4)
__global__ __launch_bounds__(256) void chunk_err_kernel(
    const float* __restrict__ kbuf, const float* __restrict__ vbuf, int n)
{
    extern __shared__ float sm[];
    float* Ms = sm;
    float* ks = sm + 64*65;
    float* e2 = ks + 64*64;
    __shared__ float gam[64], etas[64], thts[64];

    int bx = blockIdx.x;
    int b = bx >> 4, h = bx & 15;
    int tid = threadIdx.x;
    int v = tid >> 2, p = tid & 3, kb = p*16;

    const float* Mg = g_M + (size_t)(b*Hn + h)*4096;
    for (int idx = tid; idx < 4096; idx += 256)
        Ms[(idx>>6)*65 + (idx&63)] = Mg[idx];
    for (int idx = tid; idx < 4096; idx += 256) {
        int t = idx >> 6, d = idx & 63;
        ks[idx] = kbuf[(size_t)(b*Tlen + n*CSz + t)*Cdim + h*Dd + d];
    }
    if (tid < 64) {
        int tg = (b*Tlen + n*CSz + tid)*Hn + h;
        gam[tid]  = g_gamma[tg];
        etas[tid] = g_eta[tg];
        thts[tid] = g_theta[tg];
    }
    float sreg[16];
    const float* Sg = g_S + (size_t)(b*Hn + h)*4096;
    #pragma unroll
    for (int j = 0; j < 16; j++) sreg[j] = Sg[v*64 + kb + j];
    __syncthreads();

    // err2[t][v] = 2*(M k_t - v_t)[v]
    for (int t = 0; t < 64; t++) {
        float partial = 0.f;
        #pragma unroll
        for (int j = 0; j < 16; j++) partial += Ms[v*65 + kb + j] * ks[t*64 + kb + j];
        partial += __shfl_xor_sync(0xffffffffu, partial, 1);
        partial += __shfl_xor_sync(0xffffffffu, partial, 2);
        if (p == 0) {
            float vv = vbuf[(size_t)(b*Tlen + n*CSz + t)*Cdim + h*Dd + v];
            e2[t*64 + v] = 2.f*(partial - vv);
        }
    }
    __syncthreads();

    // omega window + momentum scan; store chunk_S
    for (int t = 0; t < 64; t++) {
        float ge[8]; int ki[8];
        #pragma unroll
        for (int w2 = 0; w2 < 8; w2++) {
            int iw = t - 7 + w2;
            bool ok = (iw >= 0);
            int iwc = ok ? iw : 0;
            ge[w2] = ok ? (gam[iwc] * e2[iwc*64 + v]) : 0.f;
            ki[w2] = iwc*64 + kb;
        }
        float neta = -etas[t], th = thts[t];
        size_t base = ((((size_t)b*CSz + t)*Hn + h)*Dd + v)*Dd + kb;
        #pragma unroll
        for (int j = 0; j < 16; j++) {
            float m = 0.f;
            #pragma unroll
            for (int w2 = 0; w2 < 8; w2++) m += ge[w2] * ks[ki[w2] + j];
            sreg[j] = th*sreg[j] + neta*m;
            g_chunkS[base + j] = sreg[j];
        }
    }
    float* Sgw = g_S + (size_t)(b*Hn + h)*4096;
    #pragma unroll
    for (int j = 0; j < 16; j++) Sgw[v*64 + kb + j] = sreg[j];
}

// ---------------- Polar Express (in-place on g_chunkS), one 64x64 matrix per block ----------------
// Kahan-compensated accumulation in all three matmuls: PE amplifies any
// accumulation noise by 10^2-10^3, so the dot products must sit at the fp32
// storage floor (~6e-8), not the 64-term sequential-chain level (~5e-7).
#define PE_SMEM (3*64*65*4)

#define KAHAN_STEP(P, ACCV, CMPV) do {        \
    float _y = (P) - (CMPV);                  \
    float _s = (ACCV) + _y;                   \
    (CMPV) = (_s - (ACCV)) - _y;              \
    (ACCV) = _s;                              \
} while (0)

__global__ __launch_bounds__(256) void pe_kernel()
{
    extern __shared__ float sm[];
    float* X  = sm;
    float* Aa = sm + 64*65;
    float* Tt = sm + 2*64*65;
    __shared__ float red[8];
    __shared__ float snorm;

    int tid = threadIdx.x;
    int tx = tid & 15, ty = tid >> 4;
    int i0 = ty*4, j0 = tx*4;
    float* gp = g_chunkS + (size_t)blockIdx.x * 4096;

    float lsum = 0.f;
    for (int idx = tid; idx < 4096; idx += 256) {
        float xv = gp[idx];
        X[(idx>>6)*65 + (idx&63)] = xv;
        lsum += xv*xv;
    }
    #pragma unroll
    for (int m = 16; m >= 1; m >>= 1) lsum += __shfl_xor_sync(0xffffffffu, lsum, m);
    if ((tid & 31) == 0) red[tid >> 5] = lsum;
    __syncthreads();
    if (tid < 8) {
        float r2 = red[tid];
        r2 += __shfl_xor_sync(0xffu, r2, 4);
        r2 += __shfl_xor_sync(0xffu, r2, 2);
        r2 += __shfl_xor_sync(0xffu, r2, 1);
        if (tid == 0) snorm = 1.f/((sqrtf(r2) + 1e-7f)*1.01f);
    }
    __syncthreads();
    float sc = snorm;
    for (int idx = tid; idx < 4096; idx += 256)
        X[(idx>>6)*65 + (idx&63)] *= sc;
    __syncthreads();

    #pragma unroll 1
    for (int it = 0; it < 5; it++) {
        float ca = PEC[it][0], cb = PEC[it][1], cc = PEC[it][2];
        // Aa = X X^T
        {
            float acc[4][4] = {};
            float cmp[4][4] = {};
            #pragma unroll 2
            for (int k = 0; k < 64; k++) {
                float ar[4], br[4];
                #pragma unroll
                for (int r = 0; r < 4; r++) ar[r] = X[(i0+r)*65 + k];
                #pragma unroll
                for (int c = 0; c < 4; c++) br[c] = X[(j0+c)*65 + k];
                #pragma unroll
                for (int r = 0; r < 4; r++)
                    #pragma unroll
                    for (int c = 0; c < 4; c++) {
                        float p = ar[r]*br[c];
                        KAHAN_STEP(p, acc[r][c], cmp[r][c]);
                    }
            }
            #pragma unroll
            for (int r = 0; r < 4; r++)
                #pragma unroll
                for (int c = 0; c < 4; c++)
                    Aa[(i0+r)*65 + j0 + c] = acc[r][c] - cmp[r][c];
        }
        __syncthreads();
        // Tt = Aa Aa
        {
            float acc[4][4] = {};
            float cmp[4][4] = {};
            #pragma unroll 2
            for (int k = 0; k < 64; k++) {
                float ar[4], br[4];
                #pragma unroll
                for (int r = 0; r < 4; r++) ar[r] = Aa[(i0+r)*65 + k];
                #pragma unroll
                for (int c = 0; c < 4; c++) br[c] = Aa[k*65 + j0 + c];
                #pragma unroll
                for (int r = 0; r < 4; r++)
                    #pragma unroll
                    for (int c = 0; c < 4; c++) {
                        float p = ar[r]*br[c];
                        KAHAN_STEP(p, acc[r][c], cmp[r][c]);
                    }
            }
            #pragma unroll
            for (int r = 0; r < 4; r++)
                #pragma unroll
                for (int c = 0; c < 4; c++)
                    Tt[(i0+r)*65 + j0 + c] = acc[r][c] - cmp[r][c];
        }
        __syncthreads();
        // Aa = cb*Aa + cc*Tt   (elementwise)
        for (int idx = tid; idx < 4096; idx += 256) {
            int off = (idx>>6)*65 + (idx&63);
            Aa[off] = cb*Aa[off] + cc*Tt[off];
        }
        __syncthreads();
        // Tt = ca*X + Aa X
        {
            float acc[4][4] = {};
            float cmp[4][4] = {};
            #pragma unroll 2
            for (int k = 0; k < 64; k++) {
                float ar[4], br[4];
                #pragma unroll
                for (int r = 0; r < 4; r++) ar[r] = Aa[(i0+r)*65 + k];
                #pragma unroll
                for (int c = 0; c < 4; c++) br[c] = X[k*65 + j0 + c];
                #pragma unroll
                for (int r = 0; r < 4; r++)
                    #pragma unroll
                    for (int c = 0; c < 4; c++) {
                        float p = ar[r]*br[c];
                        KAHAN_STEP(p, acc[r][c], cmp[r][c]);
                    }
            }
            #pragma unroll
            for (int r = 0; r < 4; r++)
                #pragma unroll
                for (int c = 0; c < 4; c++)
                    Tt[(i0+r)*65 + j0 + c] = ca*X[(i0+r)*65 + j0 + c]
                                           + (acc[r][c] - cmp[r][c]);
        }
        __syncthreads();
        float* tmp = X; X = Tt; Tt = tmp;
    }
    for (int idx = tid; idx < 4096; idx += 256)
        gp[idx] = X[(idx>>6)*65 + (idx&63)];
}

// ---------------- per-chunk: memory scan M_t = a_t M_{t-1} + orth_t ; y_t = M_t q_t ----------------
__global__ __launch_bounds__(256) void memscan_kernel(const float* __restrict__ qbuf, int n)
{
    __shared__ float qs[64*64];
    __shared__ float al[64];
    int bx = blockIdx.x;
    int b = bx >> 4, h = bx & 15;
    int tid = threadIdx.x;
    int v = tid >> 2, p = tid & 3, kb = p*16;

    for (int idx = tid; idx < 4096; idx += 256) {
        int t = idx >> 6, d = idx & 63;
        qs[idx] = qbuf[(size_t)(b*Tlen + n*CSz + t)*Cdim + h*Dd + d];
    }
    if (tid < 64) al[tid] = g_alpha[(b*Tlen + n*CSz + tid)*Hn + h];

    float mreg[16];
    const float* Mg = g_M + (size_t)(b*Hn + h)*4096;
    #pragma unroll
    for (int j = 0; j < 16; j++) mreg[j] = Mg[v*64 + kb + j];
    __syncthreads();

    for (int t = 0; t < 64; t++) {
        float a = al[t];
        size_t base = ((((size_t)b*CSz + t)*Hn + h)*Dd + v)*Dd + kb;
        #pragma unroll
        for (int j = 0; j < 16; j++) mreg[j] = a*mreg[j] + g_chunkS[base + j];
        float pa = 0.f;
        #pragma unroll
        for (int j = 0; j < 16; j++) pa += mreg[j]*qs[t*64 + kb + j];
        pa += __shfl_xor_sync(0xffffffffu, pa, 1);
        pa += __shfl_xor_sync(0xffffffffu, pa, 2);
        if (p == 0)
            g_y[(size_t)(b*Tlen + n*CSz + t)*Cdim + h*Dd + v] = pa;
    }
    float* Mgw = g_M + (size_t)(b*Hn + h)*4096;
    #pragma unroll
    for (int j = 0; j < 16; j++) Mgw[v*64 + kb + j] = mreg[j];
}

// ---------------- launch ----------------
extern "C" void kernel_launch(void* const* d_in, const int* in_sizes, int n_in,
                              void* d_out, int out_size)
{
    const float* x   = (const float*)d_in[0];
    const float* Wq  = (const float*)d_in[1];
    const float* Wk  = (const float*)d_in[2];
    const float* Wv  = (const float*)d_in[3];
    const float* Wo  = (const float*)d_in[4];
    const float* cqw = (const float*)d_in[5];
    const float* cqb = (const float*)d_in[6];
    const float* ckw = (const float*)d_in[7];
    const float* ckb = (const float*)d_in[8];
    const float* cvw = (const float*)d_in[9];
    const float* cvb = (const float*)d_in[10];
    const float* Wa  = (const float*)d_in[11];
    const float* We  = (const float*)d_in[12];
    const float* Wt  = (const float*)d_in[13];
    const float* Wg  = (const float*)d_in[14];
    float* out = (float*)d_out;

    cudaFuncSetAttribute(chunk_err_kernel, cudaFuncAttributeMaxDynamicSharedMemorySize, CE_SMEM);
    cudaFuncSetAttribute(pe_kernel,        cudaFuncAttributeMaxDynamicSharedMemorySize, PE_SMEM);

    float *pxq, *pxk, *pxv, *pq, *pk, *pv, *py, *pyn;
    cudaGetSymbolAddress((void**)&pxq, g_xq);
    cudaGetSymbolAddress((void**)&pxk, g_xk);
    cudaGetSymbolAddress((void**)&pxv, g_xv);
    cudaGetSymbolAddress((void**)&pq,  g_q);
    cudaGetSymbolAddress((void**)&pk,  g_k);
    cudaGetSymbolAddress((void**)&pv,  g_v);
    cudaGetSymbolAddress((void**)&py,  g_y);
    cudaGetSymbolAddress((void**)&pyn, g_yn);

    zero_state_kernel<<<(Bsz*Hn*Dd*Dd + 255)/256, 256>>>();

    dim3 gg(Cdim/64, (Bsz*Tlen)/64);
    sgemm_nt<<<gg, 256>>>(x, Wq, pxq, Bsz*Tlen, Cdim, Cdim);
    sgemm_nt<<<gg, 256>>>(x, Wk, pxk, Bsz*Tlen, Cdim, Cdim);
    sgemm_nt<<<gg, 256>>>(x, Wv, pxv, Bsz*Tlen, Cdim, Cdim);
    gates_kernel<<<Bsz*Tlen, 256>>>(x, Wa, We, Wt, Wg);
    conv_feat_kernel<<<Bsz*Tlen, 256>>>(pxq, cqw, cqb, pq, 1);
    conv_feat_kernel<<<Bsz*Tlen, 256>>>(pxk, ckw, ckb, pk, 1);
    conv_feat_kernel<<<Bsz*Tlen, 256>>>(pxv, cvw, cvb, pv, 0);

    for (int n = 0; n < NCH; n++) {
        chunk_err_kernel<<<Bsz*Hn, 256, CE_SMEM>>>(pk, pv, n);
        pe_kernel<<<Bsz*CSz*Hn, 256, PE_SMEM>>>();
        memscan_kernel<<<Bsz*Hn, 256>>>(pq, n);
    }

    ynorm_kernel<<<Bsz*Tlen, 256>>>(py, pyn);
    sgemm_nt<<<gg, 256>>>(pyn, Wo, out, Bsz*Tlen, Cdim, Cdim);
}

// round 6
// speedup vs baseline: 1.3346x; 1.3346x over previous
#include <cuda_runtime.h>
#include <cuda_bf16.h>
#include <math.h>

#define Bsz  2
#define Tlen 512
#define Cdim 1024
#define Hn   16
#define Dd   64
#define CSz  64
#define NCH  8
#define KCV  4

// ---------------- scratch (static device globals; no allocation) ----------------
__device__ float g_xq[Bsz*Tlen*Cdim];
__device__ float g_xk[Bsz*Tlen*Cdim];
__device__ float g_xv[Bsz*Tlen*Cdim];
__device__ float g_q [Bsz*Tlen*Cdim];
__device__ float g_k [Bsz*Tlen*Cdim];
__device__ float g_v [Bsz*Tlen*Cdim];
__device__ float g_alpha[Bsz*Tlen*Hn];
__device__ float g_eta  [Bsz*Tlen*Hn];
__device__ float g_theta[Bsz*Tlen*Hn];
__device__ float g_gamma[Bsz*Tlen*Hn];
__device__ float g_M[Bsz*Hn*Dd*Dd];
__device__ float g_S[Bsz*Hn*Dd*Dd];
__device__ float g_chunkS[(size_t)Bsz*CSz*Hn*Dd*Dd];   // 33.5 MB
__device__ float g_y [Bsz*Tlen*Cdim];
__device__ float g_yn[Bsz*Tlen*Cdim];

__constant__ float PEC[5][3] = {
    {8.28721201814563f, -23.595886519098837f, 17.300387312530933f},
    {4.107059111542203f, -2.9478499167379106f, 0.5448431082926601f},
    {3.9486908534822946f, -2.908902115962949f, 0.5518191394370137f},
    {3.3184196573706015f, -2.488488024314874f, 0.51004894012372f},
    {2.300652019954817f, -1.6689039845747493f, 0.4188073119525673f},
};

// ---------------- zero persistent state ----------------
__global__ void zero_state_kernel() {
    int i = blockIdx.x * blockDim.x + threadIdx.x;
    if (i < Bsz*Hn*Dd*Dd) { g_M[i] = 0.f; g_S[i] = 0.f; }
}

// ---------------- SGEMM NT: C[m,n] = sum_k A[m,k]*B[n,k] ----------------
// Two-level accumulation: 16-term tile accumulator + Kahan fold into master.
__device__ __forceinline__ void sgemm_nt_body(
    const float* __restrict__ A, const float* __restrict__ B, float* __restrict__ C,
    int M, int N, int K, int bx, int by)
{
    __shared__ float As[64][17];
    __shared__ float Bs[64][17];
    int tx = threadIdx.x & 15, ty = threadIdx.x >> 4;
    int m0 = by * 64, n0 = bx * 64;
    float acc[4][4] = {};
    float cmp[4][4] = {};
    for (int k0 = 0; k0 < K; k0 += 16) {
        #pragma unroll
        for (int i = 0; i < 4; i++) {
            int e = threadIdx.x + 256*i;
            int r = e >> 4, kk = e & 15;
            As[r][kk] = A[(size_t)(m0+r)*K + k0 + kk];
            Bs[r][kk] = B[(size_t)(n0+r)*K + k0 + kk];
        }
        __syncthreads();
        float tacc[4][4] = {};
        #pragma unroll
        for (int kk = 0; kk < 16; kk++) {
            float ar[4], br[4];
            #pragma unroll
            for (int r = 0; r < 4; r++) ar[r] = As[ty*4+r][kk];
            #pragma unroll
            for (int c = 0; c < 4; c++) br[c] = Bs[tx*4+c][kk];
            #pragma unroll
            for (int r = 0; r < 4; r++)
                #pragma unroll
                for (int c = 0; c < 4; c++)
                    tacc[r][c] += ar[r]*br[c];
        }
        #pragma unroll
        for (int r = 0; r < 4; r++)
            #pragma unroll
            for (int c = 0; c < 4; c++) {
                float y = tacc[r][c] - cmp[r][c];
                float s = acc[r][c] + y;
                cmp[r][c] = (s - acc[r][c]) - y;
                acc[r][c] = s;
            }
        __syncthreads();
    }
    #pragma unroll
    for (int r = 0; r < 4; r++)
        #pragma unroll
        for (int c = 0; c < 4; c++)
            C[(size_t)(m0+ty*4+r)*N + n0 + tx*4 + c] = acc[r][c] - cmp[r][c];
}

__global__ __launch_bounds__(256) void sgemm_nt(
    const float* __restrict__ A, const float* __restrict__ B, float* __restrict__ C,
    int M, int N, int K)
{
    sgemm_nt_body(A, B, C, M, N, K, blockIdx.x, blockIdx.y);
}

// Fused q/k/v projection: one launch, grid.z selects the weight/output pair.
__global__ __launch_bounds__(256) void sgemm_nt_qkv(
    const float* __restrict__ A,
    const float* __restrict__ Wq, const float* __restrict__ Wk, const float* __restrict__ Wv,
    float* __restrict__ Cq, float* __restrict__ Ck, float* __restrict__ Cv,
    int M, int N, int K)
{
    int z = blockIdx.z;
    const float* B = (z == 0) ? Wq : (z == 1) ? Wk : Wv;
    float*       C = (z == 0) ? Cq : (z == 1) ? Ck : Cv;
    sgemm_nt_body(A, B, C, M, N, K, blockIdx.x, blockIdx.y);
}

// ---------------- causal depthwise conv (+ optional rmsnorm+poly per head) ----------------
__global__ __launch_bounds__(256) void conv_feat_kernel(
    const float* __restrict__ xin, const float* __restrict__ w,
    const float* __restrict__ bias, float* __restrict__ outp, int do_norm)
{
    int bt = blockIdx.x;
    int b = bt / Tlen, t = bt % Tlen;
    int c0 = threadIdx.x * 4;
    float val[4];
    #pragma unroll
    for (int u = 0; u < 4; u++) {
        int c = c0 + u;
        float acc = bias[c];
        #pragma unroll
        for (int j = 0; j < KCV; j++) {
            int tt = t - (KCV-1) + j;
            if (tt >= 0) acc += w[c*KCV + j] * xin[(size_t)(b*Tlen + tt)*Cdim + c];
        }
        val[u] = acc;
    }
    if (do_norm) {
        float ss = val[0]*val[0] + val[1]*val[1] + val[2]*val[2] + val[3]*val[3];
        #pragma unroll
        for (int m = 1; m < 16; m <<= 1) ss += __shfl_xor_sync(0xffffffffu, ss, m);
        float r = rsqrtf(ss * (1.f/64.f) + 1e-6f);
        #pragma unroll
        for (int u = 0; u < 4; u++) {
            float xn = val[u] * r;
            val[u] = xn + 0.5f*xn*xn;
        }
    }
    float4* o4 = (float4*)(outp + (size_t)bt*Cdim + c0);
    *o4 = make_float4(val[0], val[1], val[2], val[3]);
}

// ---------------- final per-head rmsnorm of y ----------------
__global__ __launch_bounds__(256) void ynorm_kernel(
    const float* __restrict__ yin, float* __restrict__ outp)
{
    int bt = blockIdx.x;
    int c0 = threadIdx.x * 4;
    float val[4];
    #pragma unroll
    for (int u = 0; u < 4; u++) val[u] = yin[(size_t)bt*Cdim + c0 + u];
    float ss = val[0]*val[0] + val[1]*val[1] + val[2]*val[2] + val[3]*val[3];
    #pragma unroll
    for (int m = 1; m < 16; m <<= 1) ss += __shfl_xor_sync(0xffffffffu, ss, m);
    float r = rsqrtf(ss * (1.f/64.f) + 1e-6f);
    float4* o4 = (float4*)(outp + (size_t)bt*Cdim + c0);
    *o4 = make_float4(val[0]*r, val[1]*r, val[2]*r, val[3]*r);
}

// ---------------- gates: sigmoid(x @ W.T) for 4 weight matrices ----------------
__global__ __launch_bounds__(256) void gates_kernel(
    const float* __restrict__ x,
    const float* __restrict__ Wa, const float* __restrict__ We,
    const float* __restrict__ Wt, const float* __restrict__ Wg)
{
    __shared__ float xs[Cdim];
    int bt = blockIdx.x;
    int tid = threadIdx.x;
    #pragma unroll
    for (int i = 0; i < 4; i++) xs[tid + 256*i] = x[(size_t)bt*Cdim + tid + 256*i];
    __syncthreads();
    int oi = tid >> 2, part = tid & 3;
    int mat = oi >> 4, h = oi & 15;
    const float* W = (mat==0) ? Wa : (mat==1) ? We : (mat==2) ? Wt : Wg;
    W += h*Cdim + part*256;
    const float* xp = xs + part*256;
    float a0 = 0.f, a1 = 0.f, a2 = 0.f, a3 = 0.f;
    #pragma unroll 8
    for (int i = 0; i < 64; i++) {
        a0 += xp[i]      * W[i];
        a1 += xp[64+i]   * W[64+i];
        a2 += xp[128+i]  * W[128+i];
        a3 += xp[192+i]  * W[192+i];
    }
    float acc = (a0 + a1) + (a2 + a3);
    acc += __shfl_xor_sync(0xffffffffu, acc, 1);
    acc += __shfl_xor_sync(0xffffffffu, acc, 2);
    if (part == 0) {
        float s = 1.f/(1.f + expf(-acc));
        float* out = (mat==0) ? g_alpha : (mat==1) ? g_eta : (mat==2) ? g_theta : g_gamma;
        out[bt*Hn + h] = s;
    }
}

// ---------------- per-chunk: err, omega window, momentum scan -> g_chunkS ----------------
#define CE_SMEM ((64*65 + 64*64*2)*4)
__global__ __launch_bounds__(256) void chunk_err_kernel(
    const float* __restrict__ kbuf, const float* __restrict__ vbuf, int n)
{
    extern __shared__ float sm[];
    float* Ms = sm;
    float* ks = sm + 64*65;
    float* e2 = ks + 64*64;
    __shared__ float gam[64], etas[64], thts[64];

    int bx = blockIdx.x;
    int b = bx >> 4, h = bx & 15;
    int tid = threadIdx.x;
    int v = tid >> 2, p = tid & 3, kb = p*16;

    const float* Mg = g_M + (size_t)(b*Hn + h)*4096;
    for (int idx = tid; idx < 4096; idx += 256)
        Ms[(idx>>6)*65 + (idx&63)] = Mg[idx];
    for (int idx = tid; idx < 4096; idx += 256) {
        int t = idx >> 6, d = idx & 63;
        ks[idx] = kbuf[(size_t)(b*Tlen + n*CSz + t)*Cdim + h*Dd + d];
    }
    if (tid < 64) {
        int tg = (b*Tlen + n*CSz + tid)*Hn + h;
        gam[tid]  = g_gamma[tg];
        etas[tid] = g_eta[tg];
        thts[tid] = g_theta[tg];
    }
    float sreg[16];
    const float* Sg = g_S + (size_t)(b*Hn + h)*4096;
    #pragma unroll
    for (int j = 0; j < 16; j++) sreg[j] = Sg[v*64 + kb + j];
    __syncthreads();

    // err2[t][v] = 2*(M k_t - v_t)[v]
    for (int t = 0; t < 64; t++) {
        float partial = 0.f;
        #pragma unroll
        for (int j = 0; j < 16; j++) partial += Ms[v*65 + kb + j] * ks[t*64 + kb + j];
        partial += __shfl_xor_sync(0xffffffffu, partial, 1);
        partial += __shfl_xor_sync(0xffffffffu, partial, 2);
        if (p == 0) {
            float vv = vbuf[(size_t)(b*Tlen + n*CSz + t)*Cdim + h*Dd + v];
            e2[t*64 + v] = 2.f*(partial - vv);
        }
    }
    __syncthreads();

    // omega window + momentum scan; store chunk_S
    for (int t = 0; t < 64; t++) {
        float ge[8]; int ki[8];
        #pragma unroll
        for (int w2 = 0; w2 < 8; w2++) {
            int iw = t - 7 + w2;
            bool ok = (iw >= 0);
            int iwc = ok ? iw : 0;
            ge[w2] = ok ? (gam[iwc] * e2[iwc*64 + v]) : 0.f;
            ki[w2] = iwc*64 + kb;
        }
        float neta = -etas[t], th = thts[t];
        size_t base = ((((size_t)b*CSz + t)*Hn + h)*Dd + v)*Dd + kb;
        #pragma unroll
        for (int j = 0; j < 16; j++) {
            float m = 0.f;
            #pragma unroll
            for (int w2 = 0; w2 < 8; w2++) m += ge[w2] * ks[ki[w2] + j];
            sreg[j] = th*sreg[j] + neta*m;
            g_chunkS[base + j] = sreg[j];
        }
    }
    float* Sgw = g_S + (size_t)(b*Hn + h)*4096;
    #pragma unroll
    for (int j = 0; j < 16; j++) Sgw[v*64 + kb + j] = sreg[j];
}

// ---------------- Polar Express (in-place on g_chunkS), one 64x64 matrix per block ----------------
// Noise amplification of iteration i is prod_{j>i} a_j:  iter0 ~124x, iter1 ~30x,
// iter2 ~7.6x, iter3 ~2.3x, iter4 ~1x.  So: Kahan-compensated accumulation for
// iters 0-1 (noise -> fp32 storage floor), plain FMA with split accumulators for
// iters 2-4 (chain noise ~3.5e-7 amplified <=7.6x => <3e-6, negligible vs the
// 8.4e-4 budget).  This cuts the issue-bound instruction stream ~2x.
#define PE_SMEM (3*64*65*4)

// 64x64 * 64x64 -> per-thread 4x4 tile.  BT: B accessed transposed (row-major dot).
template<bool KAHAN, bool BT>
__device__ __forceinline__ void mm64(
    const float* __restrict__ A, const float* __restrict__ B,
    float out[4][4], int i0, int j0)
{
    float acc[4][4] = {};
    float aux[4][4] = {};   // Kahan compensation  OR  second split accumulator
    #pragma unroll 2
    for (int k = 0; k < 64; k++) {
        float ar[4], br[4];
        #pragma unroll
        for (int r = 0; r < 4; r++) ar[r] = A[(i0+r)*65 + k];
        #pragma unroll
        for (int c = 0; c < 4; c++) br[c] = BT ? B[(j0+c)*65 + k] : B[k*65 + j0 + c];
        if (KAHAN) {
            #pragma unroll
            for (int r = 0; r < 4; r++)
                #pragma unroll
                for (int c = 0; c < 4; c++) {
                    float p = ar[r]*br[c];
                    float y = p - aux[r][c];
                    float s = acc[r][c] + y;
                    aux[r][c] = (s - acc[r][c]) - y;
                    acc[r][c] = s;
                }
        } else {
            if (k & 1) {
                #pragma unroll
                for (int r = 0; r < 4; r++)
                    #pragma unroll
                    for (int c = 0; c < 4; c++) aux[r][c] += ar[r]*br[c];
            } else {
                #pragma unroll
                for (int r = 0; r < 4; r++)
                    #pragma unroll
                    for (int c = 0; c < 4; c++) acc[r][c] += ar[r]*br[c];
            }
        }
    }
    #pragma unroll
    for (int r = 0; r < 4; r++)
        #pragma unroll
        for (int c = 0; c < 4; c++)
            out[r][c] = KAHAN ? (acc[r][c] - aux[r][c]) : (acc[r][c] + aux[r][c]);
}

template<bool KAHAN>
__device__ __forceinline__ void pe_iter(
    float* X, float* Aa, float* Tt, int i0, int j0, int tid,
    float ca, float cb, float cc)
{
    float o[4][4];
    // Aa = X X^T
    mm64<KAHAN, true>(X, X, o, i0, j0);
    #pragma unroll
    for (int r = 0; r < 4; r++)
        #pragma unroll
        for (int c = 0; c < 4; c++) Aa[(i0+r)*65 + j0 + c] = o[r][c];
    __syncthreads();
    // Tt = Aa Aa
    mm64<KAHAN, false>(Aa, Aa, o, i0, j0);
    #pragma unroll
    for (int r = 0; r < 4; r++)
        #pragma unroll
        for (int c = 0; c < 4; c++) Tt[(i0+r)*65 + j0 + c] = o[r][c];
    __syncthreads();
    // Aa = cb*Aa + cc*Tt
    for (int idx = tid; idx < 4096; idx += 256) {
        int off = (idx>>6)*65 + (idx&63);
        Aa[off] = cb*Aa[off] + cc*Tt[off];
    }
    __syncthreads();
    // Tt = ca*X + Aa X
    mm64<KAHAN, false>(Aa, X, o, i0, j0);
    #pragma unroll
    for (int r = 0; r < 4; r++)
        #pragma unroll
        for (int c = 0; c < 4; c++)
            Tt[(i0+r)*65 + j0 + c] = ca*X[(i0+r)*65 + j0 + c] + o[r][c];
    __syncthreads();
}

__global__ __launch_bounds__(256) void pe_kernel()
{
    extern __shared__ float sm[];
    float* X  = sm;
    float* Aa = sm + 64*65;
    float* Tt = sm + 2*64*65;
    __shared__ float red[8];
    __shared__ float snorm;

    int tid = threadIdx.x;
    int tx = tid & 15, ty = tid >> 4;
    int i0 = ty*4, j0 = tx*4;
    float* gp = g_chunkS + (size_t)blockIdx.x * 4096;

    float lsum = 0.f;
    for (int idx = tid; idx < 4096; idx += 256) {
        float xv = gp[idx];
        X[(idx>>6)*65 + (idx&63)] = xv;
        lsum += xv*xv;
    }
    #pragma unroll
    for (int m = 16; m >= 1; m >>= 1) lsum += __shfl_xor_sync(0xffffffffu, lsum, m);
    if ((tid & 31) == 0) red[tid >> 5] = lsum;
    __syncthreads();
    if (tid < 8) {
        float r2 = red[tid];
        r2 += __shfl_xor_sync(0xffu, r2, 4);
        r2 += __shfl_xor_sync(0xffu, r2, 2);
        r2 += __shfl_xor_sync(0xffu, r2, 1);
        if (tid == 0) snorm = 1.f/((sqrtf(r2) + 1e-7f)*1.01f);
    }
    __syncthreads();
    float sc = snorm;
    for (int idx = tid; idx < 4096; idx += 256)
        X[(idx>>6)*65 + (idx&63)] *= sc;
    __syncthreads();

    #pragma unroll 1
    for (int it = 0; it < 2; it++) {
        pe_iter<true>(X, Aa, Tt, i0, j0, tid, PEC[it][0], PEC[it][1], PEC[it][2]);
        float* tmp = X; X = Tt; Tt = tmp;
    }
    #pragma unroll 1
    for (int it = 2; it < 5; it++) {
        pe_iter<false>(X, Aa, Tt, i0, j0, tid, PEC[it][0], PEC[it][1], PEC[it][2]);
        float* tmp = X; X = Tt; Tt = tmp;
    }
    for (int idx = tid; idx < 4096; idx += 256)
        gp[idx] = X[(idx>>6)*65 + (idx&63)];
}

// ---------------- per-chunk: memory scan M_t = a_t M_{t-1} + orth_t ; y_t = M_t q_t ----------------
__global__ __launch_bounds__(256) void memscan_kernel(const float* __restrict__ qbuf, int n)
{
    __shared__ float qs[64*64];
    __shared__ float al[64];
    int bx = blockIdx.x;
    int b = bx >> 4, h = bx & 15;
    int tid = threadIdx.x;
    int v = tid >> 2, p = tid & 3, kb = p*16;

    for (int idx = tid; idx < 4096; idx += 256) {
        int t = idx >> 6, d = idx & 63;
        qs[idx] = qbuf[(size_t)(b*Tlen + n*CSz + t)*Cdim + h*Dd + d];
    }
    if (tid < 64) al[tid] = g_alpha[(b*Tlen + n*CSz + tid)*Hn + h];

    float mreg[16];
    const float* Mg = g_M + (size_t)(b*Hn + h)*4096;
    #pragma unroll
    for (int j = 0; j < 16; j++) mreg[j] = Mg[v*64 + kb + j];
    __syncthreads();

    for (int t = 0; t < 64; t++) {
        float a = al[t];
        size_t base = ((((size_t)b*CSz + t)*Hn + h)*Dd + v)*Dd + kb;
        #pragma unroll
        for (int j = 0; j < 16; j++) mreg[j] = a*mreg[j] + g_chunkS[base + j];
        float pa = 0.f;
        #pragma unroll
        for (int j = 0; j < 16; j++) pa += mreg[j]*qs[t*64 + kb + j];
        pa += __shfl_xor_sync(0xffffffffu, pa, 1);
        pa += __shfl_xor_sync(0xffffffffu, pa, 2);
        if (p == 0)
            g_y[(size_t)(b*Tlen + n*CSz + t)*Cdim + h*Dd + v] = pa;
    }
    float* Mgw = g_M + (size_t)(b*Hn + h)*4096;
    #pragma unroll
    for (int j = 0; j < 16; j++) Mgw[v*64 + kb + j] = mreg[j];
}

// ---------------- launch ----------------
extern "C" void kernel_launch(void* const* d_in, const int* in_sizes, int n_in,
                              void* d_out, int out_size)
{
    const float* x   = (const float*)d_in[0];
    const float* Wq  = (const float*)d_in[1];
    const float* Wk  = (const float*)d_in[2];
    const float* Wv  = (const float*)d_in[3];
    const float* Wo  = (const float*)d_in[4];
    const float* cqw = (const float*)d_in[5];
    const float* cqb = (const float*)d_in[6];
    const float* ckw = (const float*)d_in[7];
    const float* ckb = (const float*)d_in[8];
    const float* cvw = (const float*)d_in[9];
    const float* cvb = (const float*)d_in[10];
    const float* Wa  = (const float*)d_in[11];
    const float* We  = (const float*)d_in[12];
    const float* Wt  = (const float*)d_in[13];
    const float* Wg  = (const float*)d_in[14];
    float* out = (float*)d_out;

    cudaFuncSetAttribute(chunk_err_kernel, cudaFuncAttributeMaxDynamicSharedMemorySize, CE_SMEM);
    cudaFuncSetAttribute(pe_kernel,        cudaFuncAttributeMaxDynamicSharedMemorySize, PE_SMEM);

    float *pxq, *pxk, *pxv, *pq, *pk, *pv, *py, *pyn;
    cudaGetSymbolAddress((void**)&pxq, g_xq);
    cudaGetSymbolAddress((void**)&pxk, g_xk);
    cudaGetSymbolAddress((void**)&pxv, g_xv);
    cudaGetSymbolAddress((void**)&pq,  g_q);
    cudaGetSymbolAddress((void**)&pk,  g_k);
    cudaGetSymbolAddress((void**)&pv,  g_v);
    cudaGetSymbolAddress((void**)&py,  g_y);
    cudaGetSymbolAddress((void**)&pyn, g_yn);

    zero_state_kernel<<<(Bsz*Hn*Dd*Dd + 255)/256, 256>>>();

    dim3 gq(Cdim/64, (Bsz*Tlen)/64, 3);
    sgemm_nt_qkv<<<gq, 256>>>(x, Wq, Wk, Wv, pxq, pxk, pxv, Bsz*Tlen, Cdim, Cdim);
    gates_kernel<<<Bsz*Tlen, 256>>>(x, Wa, We, Wt, Wg);
    conv_feat_kernel<<<Bsz*Tlen, 256>>>(pxq, cqw, cqb, pq, 1);
    conv_feat_kernel<<<Bsz*Tlen, 256>>>(pxk, ckw, ckb, pk, 1);
    conv_feat_kernel<<<Bsz*Tlen, 256>>>(pxv, cvw, cvb, pv, 0);

    for (int n = 0; n < NCH; n++) {
        chunk_err_kernel<<<Bsz*Hn, 256, CE_SMEM>>>(pk, pv, n);
        pe_kernel<<<Bsz*CSz*Hn, 256, PE_SMEM>>>();
        memscan_kernel<<<Bsz*Hn, 256>>>(pq, n);
    }

    ynorm_kernel<<<Bsz*Tlen, 256>>>(py, pyn);
    dim3 gg(Cdim/64, (Bsz*Tlen)/64);
    sgemm_nt<<<gg, 256>>>(pyn, Wo, out, Bsz*Tlen, Cdim, Cdim);
}

// round 8
// speedup vs baseline: 1.4087x; 1.0555x over previous
#include <cuda_runtime.h>
#include <cuda_bf16.h>
#include <math.h>

#define Bsz  2
#define Tlen 512
#define Cdim 1024
#define Hn   16
#define Dd   64
#define CSz  64
#define NCH  8
#define KCV  4

// ---------------- scratch (static device globals; no allocation) ----------------
__device__ float g_xq[Bsz*Tlen*Cdim];
__device__ float g_xk[Bsz*Tlen*Cdim];
__device__ float g_xv[Bsz*Tlen*Cdim];
__device__ float g_q [Bsz*Tlen*Cdim];
__device__ float g_k [Bsz*Tlen*Cdim];
__device__ float g_v [Bsz*Tlen*Cdim];
__device__ float g_alpha[Bsz*Tlen*Hn];
__device__ float g_eta  [Bsz*Tlen*Hn];
__device__ float g_theta[Bsz*Tlen*Hn];
__device__ float g_gamma[Bsz*Tlen*Hn];
__device__ float g_M[Bsz*Hn*Dd*Dd];
__device__ float g_S[Bsz*Hn*Dd*Dd];
__device__ float g_chunkS[(size_t)Bsz*CSz*Hn*Dd*Dd];   // 33.5 MB
__device__ float g_y [Bsz*Tlen*Cdim];
__device__ float g_yn[Bsz*Tlen*Cdim];

__constant__ float PEC[5][3] = {
    {8.28721201814563f, -23.595886519098837f, 17.300387312530933f},
    {4.107059111542203f, -2.9478499167379106f, 0.5448431082926601f},
    {3.9486908534822946f, -2.908902115962949f, 0.5518191394370137f},
    {3.3184196573706015f, -2.488488024314874f, 0.51004894012372f},
    {2.300652019954817f, -1.6689039845747493f, 0.4188073119525673f},
};

// ---------------- zero persistent state ----------------
__global__ void zero_state_kernel() {
    int i = blockIdx.x * blockDim.x + threadIdx.x;
    if (i < Bsz*Hn*Dd*Dd) { g_M[i] = 0.f; g_S[i] = 0.f; }
}

// ---------------- SGEMM NT: C[m,n] = sum_k A[m,k]*B[n,k] ----------------
// Two-level accumulation: 16-term tile accumulator + Kahan fold into master.
__device__ __forceinline__ void sgemm_nt_body(
    const float* __restrict__ A, const float* __restrict__ B, float* __restrict__ C,
    int M, int N, int K, int bx, int by)
{
    __shared__ float As[64][17];
    __shared__ float Bs[64][17];
    int tx = threadIdx.x & 15, ty = threadIdx.x >> 4;
    int m0 = by * 64, n0 = bx * 64;
    float acc[4][4] = {};
    float cmp[4][4] = {};
    for (int k0 = 0; k0 < K; k0 += 16) {
        #pragma unroll
        for (int i = 0; i < 4; i++) {
            int e = threadIdx.x + 256*i;
            int r = e >> 4, kk = e & 15;
            As[r][kk] = A[(size_t)(m0+r)*K + k0 + kk];
            Bs[r][kk] = B[(size_t)(n0+r)*K + k0 + kk];
        }
        __syncthreads();
        float tacc[4][4] = {};
        #pragma unroll
        for (int kk = 0; kk < 16; kk++) {
            float ar[4], br[4];
            #pragma unroll
            for (int r = 0; r < 4; r++) ar[r] = As[ty*4+r][kk];
            #pragma unroll
            for (int c = 0; c < 4; c++) br[c] = Bs[tx*4+c][kk];
            #pragma unroll
            for (int r = 0; r < 4; r++)
                #pragma unroll
                for (int c = 0; c < 4; c++)
                    tacc[r][c] += ar[r]*br[c];
        }
        #pragma unroll
        for (int r = 0; r < 4; r++)
            #pragma unroll
            for (int c = 0; c < 4; c++) {
                float y = tacc[r][c] - cmp[r][c];
                float s = acc[r][c] + y;
                cmp[r][c] = (s - acc[r][c]) - y;
                acc[r][c] = s;
            }
        __syncthreads();
    }
    #pragma unroll
    for (int r = 0; r < 4; r++)
        #pragma unroll
        for (int c = 0; c < 4; c++)
            C[(size_t)(m0+ty*4+r)*N + n0 + tx*4 + c] = acc[r][c] - cmp[r][c];
}

__global__ __launch_bounds__(256) void sgemm_nt(
    const float* __restrict__ A, const float* __restrict__ B, float* __restrict__ C,
    int M, int N, int K)
{
    sgemm_nt_body(A, B, C, M, N, K, blockIdx.x, blockIdx.y);
}

// Fused q/k/v projection: one launch, grid.z selects the weight/output pair.
__global__ __launch_bounds__(256) void sgemm_nt_qkv(
    const float* __restrict__ A,
    const float* __restrict__ Wq, const float* __restrict__ Wk, const float* __restrict__ Wv,
    float* __restrict__ Cq, float* __restrict__ Ck, float* __restrict__ Cv,
    int M, int N, int K)
{
    int z = blockIdx.z;
    const float* B = (z == 0) ? Wq : (z == 1) ? Wk : Wv;
    float*       C = (z == 0) ? Cq : (z == 1) ? Ck : Cv;
    sgemm_nt_body(A, B, C, M, N, K, blockIdx.x, blockIdx.y);
}

// ---------------- causal depthwise conv (+ optional rmsnorm+poly per head) ----------------
__global__ __launch_bounds__(256) void conv_feat_kernel(
    const float* __restrict__ xin, const float* __restrict__ w,
    const float* __restrict__ bias, float* __restrict__ outp, int do_norm)
{
    int bt = blockIdx.x;
    int b = bt / Tlen, t = bt % Tlen;
    int c0 = threadIdx.x * 4;
    float val[4];
    #pragma unroll
    for (int u = 0; u < 4; u++) {
        int c = c0 + u;
        float acc = bias[c];
        #pragma unroll
        for (int j = 0; j < KCV; j++) {
            int tt = t - (KCV-1) + j;
            if (tt >= 0) acc += w[c*KCV + j] * xin[(size_t)(b*Tlen + tt)*Cdim + c];
        }
        val[u] = acc;
    }
    if (do_norm) {
        float ss = val[0]*val[0] + val[1]*val[1] + val[2]*val[2] + val[3]*val[3];
        #pragma unroll
        for (int m = 1; m < 16; m <<= 1) ss += __shfl_xor_sync(0xffffffffu, ss, m);
        float r = rsqrtf(ss * (1.f/64.f) + 1e-6f);
        #pragma unroll
        for (int u = 0; u < 4; u++) {
            float xn = val[u] * r;
            val[u] = xn + 0.5f*xn*xn;
        }
    }
    float4* o4 = (float4*)(outp + (size_t)bt*Cdim + c0);
    *o4 = make_float4(val[0], val[1], val[2], val[3]);
}

// ---------------- final per-head rmsnorm of y ----------------
__global__ __launch_bounds__(256) void ynorm_kernel(
    const float* __restrict__ yin, float* __restrict__ outp)
{
    int bt = blockIdx.x;
    int c0 = threadIdx.x * 4;
    float val[4];
    #pragma unroll
    for (int u = 0; u < 4; u++) val[u] = yin[(size_t)bt*Cdim + c0 + u];
    float ss = val[0]*val[0] + val[1]*val[1] + val[2]*val[2] + val[3]*val[3];
    #pragma unroll
    for (int m = 1; m < 16; m <<= 1) ss += __shfl_xor_sync(0xffffffffu, ss, m);
    float r = rsqrtf(ss * (1.f/64.f) + 1e-6f);
    float4* o4 = (float4*)(outp + (size_t)bt*Cdim + c0);
    *o4 = make_float4(val[0]*r, val[1]*r, val[2]*r, val[3]*r);
}

// ---------------- gates: sigmoid(x @ W.T) for 4 weight matrices ----------------
__global__ __launch_bounds__(256) void gates_kernel(
    const float* __restrict__ x,
    const float* __restrict__ Wa, const float* __restrict__ We,
    const float* __restrict__ Wt, const float* __restrict__ Wg)
{
    __shared__ float xs[Cdim];
    int bt = blockIdx.x;
    int tid = threadIdx.x;
    #pragma unroll
    for (int i = 0; i < 4; i++) xs[tid + 256*i] = x[(size_t)bt*Cdim + tid + 256*i];
    __syncthreads();
    int oi = tid >> 2, part = tid & 3;
    int mat = oi >> 4, h = oi & 15;
    const float* W = (mat==0) ? Wa : (mat==1) ? We : (mat==2) ? Wt : Wg;
    W += h*Cdim + part*256;
    const float* xp = xs + part*256;
    float a0 = 0.f, a1 = 0.f, a2 = 0.f, a3 = 0.f;
    #pragma unroll 8
    for (int i = 0; i < 64; i++) {
        a0 += xp[i]      * W[i];
        a1 += xp[64+i]   * W[64+i];
        a2 += xp[128+i]  * W[128+i];
        a3 += xp[192+i]  * W[192+i];
    }
    float acc = (a0 + a1) + (a2 + a3);
    acc += __shfl_xor_sync(0xffffffffu, acc, 1);
    acc += __shfl_xor_sync(0xffffffffu, acc, 2);
    if (part == 0) {
        float s = 1.f/(1.f + expf(-acc));
        float* out = (mat==0) ? g_alpha : (mat==1) ? g_eta : (mat==2) ? g_theta : g_gamma;
        out[bt*Hn + h] = s;
    }
}

// ---------------- per-chunk: err, omega window, momentum scan -> g_chunkS ----------------
#define CE_SMEM ((64*65 + 64*64*2)*4)
__global__ __launch_bounds__(256) void chunk_err_kernel(
    const float* __restrict__ kbuf, const float* __restrict__ vbuf, int n)
{
    extern __shared__ float sm[];
    float* Ms = sm;
    float* ks = sm + 64*65;
    float* e2 = ks + 64*64;
    __shared__ float gam[64], etas[64], thts[64];

    int bx = blockIdx.x;
    int b = bx >> 4, h = bx & 15;
    int tid = threadIdx.x;
    int v = tid >> 2, p = tid & 3, kb = p*16;

    const float* Mg = g_M + (size_t)(b*Hn + h)*4096;
    for (int idx = tid; idx < 4096; idx += 256)
        Ms[(idx>>6)*65 + (idx&63)] = Mg[idx];
    for (int idx = tid; idx < 4096; idx += 256) {
        int t = idx >> 6, d = idx & 63;
        ks[idx] = kbuf[(size_t)(b*Tlen + n*CSz + t)*Cdim + h*Dd + d];
    }
    if (tid < 64) {
        int tg = (b*Tlen + n*CSz + tid)*Hn + h;
        gam[tid]  = g_gamma[tg];
        etas[tid] = g_eta[tg];
        thts[tid] = g_theta[tg];
    }
    float sreg[16];
    const float* Sg = g_S + (size_t)(b*Hn + h)*4096;
    #pragma unroll
    for (int j = 0; j < 16; j++) sreg[j] = Sg[v*64 + kb + j];
    __syncthreads();

    // err2[t][v] = 2*(M k_t - v_t)[v]
    for (int t = 0; t < 64; t++) {
        float partial = 0.f;
        #pragma unroll
        for (int j = 0; j < 16; j++) partial += Ms[v*65 + kb + j] * ks[t*64 + kb + j];
        partial += __shfl_xor_sync(0xffffffffu, partial, 1);
        partial += __shfl_xor_sync(0xffffffffu, partial, 2);
        if (p == 0) {
            float vv = vbuf[(size_t)(b*Tlen + n*CSz + t)*Cdim + h*Dd + v];
            e2[t*64 + v] = 2.f*(partial - vv);
        }
    }
    __syncthreads();

    // omega window + momentum scan; store chunk_S
    for (int t = 0; t < 64; t++) {
        float ge[8]; int ki[8];
        #pragma unroll
        for (int w2 = 0; w2 < 8; w2++) {
            int iw = t - 7 + w2;
            bool ok = (iw >= 0);
            int iwc = ok ? iw : 0;
            ge[w2] = ok ? (gam[iwc] * e2[iwc*64 + v]) : 0.f;
            ki[w2] = iwc*64 + kb;
        }
        float neta = -etas[t], th = thts[t];
        size_t base = ((((size_t)b*CSz + t)*Hn + h)*Dd + v)*Dd + kb;
        #pragma unroll
        for (int j = 0; j < 16; j++) {
            float m = 0.f;
            #pragma unroll
            for (int w2 = 0; w2 < 8; w2++) m += ge[w2] * ks[ki[w2] + j];
            sreg[j] = th*sreg[j] + neta*m;
            g_chunkS[base + j] = sreg[j];
        }
    }
    float* Sgw = g_S + (size_t)(b*Hn + h)*4096;
    #pragma unroll
    for (int j = 0; j < 16; j++) Sgw[v*64 + kb + j] = sreg[j];
}

// ---------------- Polar Express (in-place on g_chunkS), one 64x64 matrix per block ----------------
// Noise amplification of iteration i is prod_{j>i} a_j: iter0 ~124x, iter1 ~30x,
// iter2 ~7.6x, iter3 ~2.3x, iter4 ~1x.  Kahan-compensated accumulation for iter 0
// ONLY (its amplified noise is the one that can breach 1e-3); plain FMA with split
// accumulators for iters 1-4 (chain noise ~3.5e-7, amplified <=30x => <=1.1e-5,
// negligible vs the ~8.5e-4 budget).  PE is fma-pipe bound: Kahan mm = 4096
// fma-pipe ops/thread, plain mm = 1024; this mix gives 24.6k vs round-6's 33.8k.
#define PE_SMEM (3*64*65*4)

// 64x64 * 64x64 -> per-thread 4x4 tile.  BT: B accessed transposed (row-major dot).
template<bool KAHAN, bool BT>
__device__ __forceinline__ void mm64(
    const float* __restrict__ A, const float* __restrict__ B,
    float out[4][4], int i0, int j0)
{
    float acc[4][4] = {};
    float aux[4][4] = {};   // Kahan compensation  OR  second split accumulator
    #pragma unroll 2
    for (int k = 0; k < 64; k++) {
        float ar[4], br[4];
        #pragma unroll
        for (int r = 0; r < 4; r++) ar[r] = A[(i0+r)*65 + k];
        #pragma unroll
        for (int c = 0; c < 4; c++) br[c] = BT ? B[(j0+c)*65 + k] : B[k*65 + j0 + c];
        if (KAHAN) {
            #pragma unroll
            for (int r = 0; r < 4; r++)
                #pragma unroll
                for (int c = 0; c < 4; c++) {
                    float p = ar[r]*br[c];
                    float y = p - aux[r][c];
                    float s = acc[r][c] + y;
                    aux[r][c] = (s - acc[r][c]) - y;
                    acc[r][c] = s;
                }
        } else {
            if (k & 1) {
                #pragma unroll
                for (int r = 0; r < 4; r++)
                    #pragma unroll
                    for (int c = 0; c < 4; c++) aux[r][c] += ar[r]*br[c];
            } else {
                #pragma unroll
                for (int r = 0; r < 4; r++)
                    #pragma unroll
                    for (int c = 0; c < 4; c++) acc[r][c] += ar[r]*br[c];
            }
        }
    }
    #pragma unroll
    for (int r = 0; r < 4; r++)
        #pragma unroll
        for (int c = 0; c < 4; c++)
            out[r][c] = KAHAN ? (acc[r][c] - aux[r][c]) : (acc[r][c] + aux[r][c]);
}

template<bool KAHAN>
__device__ __forceinline__ void pe_iter(
    float* X, float* Aa, float* Tt, int i0, int j0, int tid,
    float ca, float cb, float cc)
{
    float o[4][4];
    // Aa = X X^T
    mm64<KAHAN, true>(X, X, o, i0, j0);
    #pragma unroll
    for (int r = 0; r < 4; r++)
        #pragma unroll
        for (int c = 0; c < 4; c++) Aa[(i0+r)*65 + j0 + c] = o[r][c];
    __syncthreads();
    // Tt = Aa Aa
    mm64<KAHAN, false>(Aa, Aa, o, i0, j0);
    #pragma unroll
    for (int r = 0; r < 4; r++)
        #pragma unroll
        for (int c = 0; c < 4; c++) Tt[(i0+r)*65 + j0 + c] = o[r][c];
    __syncthreads();
    // Aa = cb*Aa + cc*Tt
    for (int idx = tid; idx < 4096; idx += 256) {
        int off = (idx>>6)*65 + (idx&63);
        Aa[off] = cb*Aa[off] + cc*Tt[off];
    }
    __syncthreads();
    // Tt = ca*X + Aa X
    mm64<KAHAN, false>(Aa, X, o, i0, j0);
    #pragma unroll
    for (int r = 0; r < 4; r++)
        #pragma unroll
        for (int c = 0; c < 4; c++)
            Tt[(i0+r)*65 + j0 + c] = ca*X[(i0+r)*65 + j0 + c] + o[r][c];
    __syncthreads();
}

__global__ __launch_bounds__(256) void pe_kernel()
{
    extern __shared__ float sm[];
    float* X  = sm;
    float* Aa = sm + 64*65;
    float* Tt = sm + 2*64*65;
    __shared__ float red[8];
    __shared__ float snorm;

    int tid = threadIdx.x;
    int tx = tid & 15, ty = tid >> 4;
    int i0 = ty*4, j0 = tx*4;
    float* gp = g_chunkS + (size_t)blockIdx.x * 4096;

    float lsum = 0.f;
    for (int idx = tid; idx < 4096; idx += 256) {
        float xv = gp[idx];
        X[(idx>>6)*65 + (idx&63)] = xv;
        lsum += xv*xv;
    }
    #pragma unroll
    for (int m = 16; m >= 1; m >>= 1) lsum += __shfl_xor_sync(0xffffffffu, lsum, m);
    if ((tid & 31) == 0) red[tid >> 5] = lsum;
    __syncthreads();
    if (tid < 8) {
        float r2 = red[tid];
        r2 += __shfl_xor_sync(0xffu, r2, 4);
        r2 += __shfl_xor_sync(0xffu, r2, 2);
        r2 += __shfl_xor_sync(0xffu, r2, 1);
        if (tid == 0) snorm = 1.f/((sqrtf(r2) + 1e-7f)*1.01f);
    }
    __syncthreads();
    float sc = snorm;
    for (int idx = tid; idx < 4096; idx += 256)
        X[(idx>>6)*65 + (idx&63)] *= sc;
    __syncthreads();

    // iter 0: Kahan (amplified ~124x downstream)
    pe_iter<true>(X, Aa, Tt, i0, j0, tid, PEC[0][0], PEC[0][1], PEC[0][2]);
    { float* tmp = X; X = Tt; Tt = tmp; }
    // iters 1-4: plain split-accumulator FMA
    #pragma unroll 1
    for (int it = 1; it < 5; it++) {
        pe_iter<false>(X, Aa, Tt, i0, j0, tid, PEC[it][0], PEC[it][1], PEC[it][2]);
        float* tmp = X; X = Tt; Tt = tmp;
    }
    for (int idx = tid; idx < 4096; idx += 256)
        gp[idx] = X[(idx>>6)*65 + (idx&63)];
}

// ---------------- per-chunk: memory scan M_t = a_t M_{t-1} + orth_t ; y_t = M_t q_t ----------------
__global__ __launch_bounds__(256) void memscan_kernel(const float* __restrict__ qbuf, int n)
{
    __shared__ float qs[64*64];
    __shared__ float al[64];
    int bx = blockIdx.x;
    int b = bx >> 4, h = bx & 15;
    int tid = threadIdx.x;
    int v = tid >> 2, p = tid & 3, kb = p*16;

    for (int idx = tid; idx < 4096; idx += 256) {
        int t = idx >> 6, d = idx & 63;
        qs[idx] = qbuf[(size_t)(b*Tlen + n*CSz + t)*Cdim + h*Dd + d];
    }
    if (tid < 64) al[tid] = g_alpha[(b*Tlen + n*CSz + tid)*Hn + h];

    float mreg[16];
    const float* Mg = g_M + (size_t)(b*Hn + h)*4096;
    #pragma unroll
    for (int j = 0; j < 16; j++) mreg[j] = Mg[v*64 + kb + j];
    __syncthreads();

    for (int t = 0; t < 64; t++) {
        float a = al[t];
        size_t base = ((((size_t)b*CSz + t)*Hn + h)*Dd + v)*Dd + kb;
        #pragma unroll
        for (int j = 0; j < 16; j++) mreg[j] = a*mreg[j] + g_chunkS[base + j];
        float pa = 0.f;
        #pragma unroll
        for (int j = 0; j < 16; j++) pa += mreg[j]*qs[t*64 + kb + j];
        pa += __shfl_xor_sync(0xffffffffu, pa, 1);
        pa += __shfl_xor_sync(0xffffffffu, pa, 2);
        if (p == 0)
            g_y[(size_t)(b*Tlen + n*CSz + t)*Cdim + h*Dd + v] = pa;
    }
    float* Mgw = g_M + (size_t)(b*Hn + h)*4096;
    #pragma unroll
    for (int j = 0; j < 16; j++) Mgw[v*64 + kb + j] = mreg[j];
}

// ---------------- launch ----------------
extern "C" void kernel_launch(void* const* d_in, const int* in_sizes, int n_in,
                              void* d_out, int out_size)
{
    const float* x   = (const float*)d_in[0];
    const float* Wq  = (const float*)d_in[1];
    const float* Wk  = (const float*)d_in[2];
    const float* Wv  = (const float*)d_in[3];
    const float* Wo  = (const float*)d_in[4];
    const float* cqw = (const float*)d_in[5];
    const float* cqb = (const float*)d_in[6];
    const float* ckw = (const float*)d_in[7];
    const float* ckb = (const float*)d_in[8];
    const float* cvw = (const float*)d_in[9];
    const float* cvb = (const float*)d_in[10];
    const float* Wa  = (const float*)d_in[11];
    const float* We  = (const float*)d_in[12];
    const float* Wt  = (const float*)d_in[13];
    const float* Wg  = (const float*)d_in[14];
    float* out = (float*)d_out;

    cudaFuncSetAttribute(chunk_err_kernel, cudaFuncAttributeMaxDynamicSharedMemorySize, CE_SMEM);
    cudaFuncSetAttribute(pe_kernel,        cudaFuncAttributeMaxDynamicSharedMemorySize, PE_SMEM);

    float *pxq, *pxk, *pxv, *pq, *pk, *pv, *py, *pyn;
    cudaGetSymbolAddress((void**)&pxq, g_xq);
    cudaGetSymbolAddress((void**)&pxk, g_xk);
    cudaGetSymbolAddress((void**)&pxv, g_xv);
    cudaGetSymbolAddress((void**)&pq,  g_q);
    cudaGetSymbolAddress((void**)&pk,  g_k);
    cudaGetSymbolAddress((void**)&pv,  g_v);
    cudaGetSymbolAddress((void**)&py,  g_y);
    cudaGetSymbolAddress((void**)&pyn, g_yn);

    zero_state_kernel<<<(Bsz*Hn*Dd*Dd + 255)/256, 256>>>();

    dim3 gq(Cdim/64, (Bsz*Tlen)/64, 3);
    sgemm_nt_qkv<<<gq, 256>>>(x, Wq, Wk, Wv, pxq, pxk, pxv, Bsz*Tlen, Cdim, Cdim);
    gates_kernel<<<Bsz*Tlen, 256>>>(x, Wa, We, Wt, Wg);
    conv_feat_kernel<<<Bsz*Tlen, 256>>>(pxq, cqw, cqb, pq, 1);
    conv_feat_kernel<<<Bsz*Tlen, 256>>>(pxk, ckw, ckb, pk, 1);
    conv_feat_kernel<<<Bsz*Tlen, 256>>>(pxv, cvw, cvb, pv, 0);

    for (int n = 0; n < NCH; n++) {
        chunk_err_kernel<<<Bsz*Hn, 256, CE_SMEM>>>(pk, pv, n);
        pe_kernel<<<Bsz*CSz*Hn, 256, PE_SMEM>>>();
        memscan_kernel<<<Bsz*Hn, 256>>>(pq, n);
    }

    ynorm_kernel<<<Bsz*Tlen, 256>>>(py, pyn);
    dim3 gg(Cdim/64, (Bsz*Tlen)/64);
    sgemm_nt<<<gg, 256>>>(pyn, Wo, out, Bsz*Tlen, Cdim, Cdim);
}

// round 9
// speedup vs baseline: 1.5057x; 1.0689x over previous
#include <cuda_runtime.h>
#include <cuda_bf16.h>
#include <math.h>

#define Bsz  2
#define Tlen 512
#define Cdim 1024
#define Hn   16
#define Dd   64
#define CSz  64
#define NCH  8
#define KCV  4

// ---------------- scratch (static device globals; no allocation) ----------------
__device__ float g_xq[Bsz*Tlen*Cdim];
__device__ float g_xk[Bsz*Tlen*Cdim];
__device__ float g_xv[Bsz*Tlen*Cdim];
__device__ float g_q [Bsz*Tlen*Cdim];
__device__ float g_k [Bsz*Tlen*Cdim];
__device__ float g_v [Bsz*Tlen*Cdim];
__device__ float g_alpha[Bsz*Tlen*Hn];
__device__ float g_eta  [Bsz*Tlen*Hn];
__device__ float g_theta[Bsz*Tlen*Hn];
__device__ float g_gamma[Bsz*Tlen*Hn];
__device__ float g_M[Bsz*Hn*Dd*Dd];
__device__ float g_S[Bsz*Hn*Dd*Dd];
__device__ float g_chunkS[(size_t)Bsz*CSz*Hn*Dd*Dd];   // 33.5 MB
__device__ float g_y [Bsz*Tlen*Cdim];
__device__ float g_yn[Bsz*Tlen*Cdim];

__constant__ float PEC[5][3] = {
    {8.28721201814563f, -23.595886519098837f, 17.300387312530933f},
    {4.107059111542203f, -2.9478499167379106f, 0.5448431082926601f},
    {3.9486908534822946f, -2.908902115962949f, 0.5518191394370137f},
    {3.3184196573706015f, -2.488488024314874f, 0.51004894012372f},
    {2.300652019954817f, -1.6689039845747493f, 0.4188073119525673f},
};

// ---------------- zero persistent state ----------------
__global__ void zero_state_kernel() {
    int i = blockIdx.x * blockDim.x + threadIdx.x;
    if (i < Bsz*Hn*Dd*Dd) { g_M[i] = 0.f; g_S[i] = 0.f; }
}

// ---------------- SGEMM NT: C[m,n] = sum_k A[m,k]*B[n,k] ----------------
__device__ __forceinline__ void sgemm_nt_body(
    const float* __restrict__ A, const float* __restrict__ B, float* __restrict__ C,
    int M, int N, int K, int bx, int by)
{
    __shared__ float As[64][17];
    __shared__ float Bs[64][17];
    int tx = threadIdx.x & 15, ty = threadIdx.x >> 4;
    int m0 = by * 64, n0 = bx * 64;
    float acc[4][4] = {};
    float cmp[4][4] = {};
    for (int k0 = 0; k0 < K; k0 += 16) {
        #pragma unroll
        for (int i = 0; i < 4; i++) {
            int e = threadIdx.x + 256*i;
            int r = e >> 4, kk = e & 15;
            As[r][kk] = A[(size_t)(m0+r)*K + k0 + kk];
            Bs[r][kk] = B[(size_t)(n0+r)*K + k0 + kk];
        }
        __syncthreads();
        float tacc[4][4] = {};
        #pragma unroll
        for (int kk = 0; kk < 16; kk++) {
            float ar[4], br[4];
            #pragma unroll
            for (int r = 0; r < 4; r++) ar[r] = As[ty*4+r][kk];
            #pragma unroll
            for (int c = 0; c < 4; c++) br[c] = Bs[tx*4+c][kk];
            #pragma unroll
            for (int r = 0; r < 4; r++)
                #pragma unroll
                for (int c = 0; c < 4; c++)
                    tacc[r][c] += ar[r]*br[c];
        }
        #pragma unroll
        for (int r = 0; r < 4; r++)
            #pragma unroll
            for (int c = 0; c < 4; c++) {
                float y = tacc[r][c] - cmp[r][c];
                float s = acc[r][c] + y;
                cmp[r][c] = (s - acc[r][c]) - y;
                acc[r][c] = s;
            }
        __syncthreads();
    }
    #pragma unroll
    for (int r = 0; r < 4; r++)
        #pragma unroll
        for (int c = 0; c < 4; c++)
            C[(size_t)(m0+ty*4+r)*N + n0 + tx*4 + c] = acc[r][c] - cmp[r][c];
}

__global__ __launch_bounds__(256) void sgemm_nt(
    const float* __restrict__ A, const float* __restrict__ B, float* __restrict__ C,
    int M, int N, int K)
{
    sgemm_nt_body(A, B, C, M, N, K, blockIdx.x, blockIdx.y);
}

__global__ __launch_bounds__(256) void sgemm_nt_qkv(
    const float* __restrict__ A,
    const float* __restrict__ Wq, const float* __restrict__ Wk, const float* __restrict__ Wv,
    float* __restrict__ Cq, float* __restrict__ Ck, float* __restrict__ Cv,
    int M, int N, int K)
{
    int z = blockIdx.z;
    const float* B = (z == 0) ? Wq : (z == 1) ? Wk : Wv;
    float*       C = (z == 0) ? Cq : (z == 1) ? Ck : Cv;
    sgemm_nt_body(A, B, C, M, N, K, blockIdx.x, blockIdx.y);
}

// ---------------- causal depthwise conv (+ optional rmsnorm+poly per head) ----------------
__global__ __launch_bounds__(256) void conv_feat_kernel(
    const float* __restrict__ xin, const float* __restrict__ w,
    const float* __restrict__ bias, float* __restrict__ outp, int do_norm)
{
    int bt = blockIdx.x;
    int b = bt / Tlen, t = bt % Tlen;
    int c0 = threadIdx.x * 4;
    float val[4];
    #pragma unroll
    for (int u = 0; u < 4; u++) {
        int c = c0 + u;
        float acc = bias[c];
        #pragma unroll
        for (int j = 0; j < KCV; j++) {
            int tt = t - (KCV-1) + j;
            if (tt >= 0) acc += w[c*KCV + j] * xin[(size_t)(b*Tlen + tt)*Cdim + c];
        }
        val[u] = acc;
    }
    if (do_norm) {
        float ss = val[0]*val[0] + val[1]*val[1] + val[2]*val[2] + val[3]*val[3];
        #pragma unroll
        for (int m = 1; m < 16; m <<= 1) ss += __shfl_xor_sync(0xffffffffu, ss, m);
        float r = rsqrtf(ss * (1.f/64.f) + 1e-6f);
        #pragma unroll
        for (int u = 0; u < 4; u++) {
            float xn = val[u] * r;
            val[u] = xn + 0.5f*xn*xn;
        }
    }
    float4* o4 = (float4*)(outp + (size_t)bt*Cdim + c0);
    *o4 = make_float4(val[0], val[1], val[2], val[3]);
}

// ---------------- final per-head rmsnorm of y ----------------
__global__ __launch_bounds__(256) void ynorm_kernel(
    const float* __restrict__ yin, float* __restrict__ outp)
{
    int bt = blockIdx.x;
    int c0 = threadIdx.x * 4;
    float val[4];
    #pragma unroll
    for (int u = 0; u < 4; u++) val[u] = yin[(size_t)bt*Cdim + c0 + u];
    float ss = val[0]*val[0] + val[1]*val[1] + val[2]*val[2] + val[3]*val[3];
    #pragma unroll
    for (int m = 1; m < 16; m <<= 1) ss += __shfl_xor_sync(0xffffffffu, ss, m);
    float r = rsqrtf(ss * (1.f/64.f) + 1e-6f);
    float4* o4 = (float4*)(outp + (size_t)bt*Cdim + c0);
    *o4 = make_float4(val[0]*r, val[1]*r, val[2]*r, val[3]*r);
}

// ---------------- gates: sigmoid(x @ W.T) for 4 weight matrices ----------------
__global__ __launch_bounds__(256) void gates_kernel(
    const float* __restrict__ x,
    const float* __restrict__ Wa, const float* __restrict__ We,
    const float* __restrict__ Wt, const float* __restrict__ Wg)
{
    __shared__ float xs[Cdim];
    int bt = blockIdx.x;
    int tid = threadIdx.x;
    #pragma unroll
    for (int i = 0; i < 4; i++) xs[tid + 256*i] = x[(size_t)bt*Cdim + tid + 256*i];
    __syncthreads();
    int oi = tid >> 2, part = tid & 3;
    int mat = oi >> 4, h = oi & 15;
    const float* W = (mat==0) ? Wa : (mat==1) ? We : (mat==2) ? Wt : Wg;
    W += h*Cdim + part*256;
    const float* xp = xs + part*256;
    float a0 = 0.f, a1 = 0.f, a2 = 0.f, a3 = 0.f;
    #pragma unroll 8
    for (int i = 0; i < 64; i++) {
        a0 += xp[i]      * W[i];
        a1 += xp[64+i]   * W[64+i];
        a2 += xp[128+i]  * W[128+i];
        a3 += xp[192+i]  * W[192+i];
    }
    float acc = (a0 + a1) + (a2 + a3);
    acc += __shfl_xor_sync(0xffffffffu, acc, 1);
    acc += __shfl_xor_sync(0xffffffffu, acc, 2);
    if (part == 0) {
        float s = 1.f/(1.f + expf(-acc));
        float* out = (mat==0) ? g_alpha : (mat==1) ? g_eta : (mat==2) ? g_theta : g_gamma;
        out[bt*Hn + h] = s;
    }
}

// ---------------- per-chunk: err, omega window, momentum scan -> g_chunkS ----------------
#define CE_SMEM ((64*65 + 64*64*2)*4)
__global__ __launch_bounds__(256) void chunk_err_kernel(
    const float* __restrict__ kbuf, const float* __restrict__ vbuf, int n)
{
    extern __shared__ float sm[];
    float* Ms = sm;
    float* ks = sm + 64*65;
    float* e2 = ks + 64*64;
    __shared__ float gam[64], etas[64], thts[64];

    int bx = blockIdx.x;
    int b = bx >> 4, h = bx & 15;
    int tid = threadIdx.x;
    int v = tid >> 2, p = tid & 3, kb = p*16;

    const float* Mg = g_M + (size_t)(b*Hn + h)*4096;
    for (int idx = tid; idx < 4096; idx += 256)
        Ms[(idx>>6)*65 + (idx&63)] = Mg[idx];
    for (int idx = tid; idx < 4096; idx += 256) {
        int t = idx >> 6, d = idx & 63;
        ks[idx] = kbuf[(size_t)(b*Tlen + n*CSz + t)*Cdim + h*Dd + d];
    }
    if (tid < 64) {
        int tg = (b*Tlen + n*CSz + tid)*Hn + h;
        gam[tid]  = g_gamma[tg];
        etas[tid] = g_eta[tg];
        thts[tid] = g_theta[tg];
    }
    float sreg[16];
    const float* Sg = g_S + (size_t)(b*Hn + h)*4096;
    #pragma unroll
    for (int j = 0; j < 16; j++) sreg[j] = Sg[v*64 + kb + j];
    __syncthreads();

    // err2[t][v] = 2*(M k_t - v_t)[v]
    for (int t = 0; t < 64; t++) {
        float partial = 0.f;
        #pragma unroll
        for (int j = 0; j < 16; j++) partial += Ms[v*65 + kb + j] * ks[t*64 + kb + j];
        partial += __shfl_xor_sync(0xffffffffu, partial, 1);
        partial += __shfl_xor_sync(0xffffffffu, partial, 2);
        if (p == 0) {
            float vv = vbuf[(size_t)(b*Tlen + n*CSz + t)*Cdim + h*Dd + v];
            e2[t*64 + v] = 2.f*(partial - vv);
        }
    }
    __syncthreads();

    // omega window + momentum scan; store chunk_S
    for (int t = 0; t < 64; t++) {
        float ge[8]; int ki[8];
        #pragma unroll
        for (int w2 = 0; w2 < 8; w2++) {
            int iw = t - 7 + w2;
            bool ok = (iw >= 0);
            int iwc = ok ? iw : 0;
            ge[w2] = ok ? (gam[iwc] * e2[iwc*64 + v]) : 0.f;
            ki[w2] = iwc*64 + kb;
        }
        float neta = -etas[t], th = thts[t];
        size_t base = ((((size_t)b*CSz + t)*Hn + h)*Dd + v)*Dd + kb;
        #pragma unroll
        for (int j = 0; j < 16; j++) {
            float m = 0.f;
            #pragma unroll
            for (int w2 = 0; w2 < 8; w2++) m += ge[w2] * ks[ki[w2] + j];
            sreg[j] = th*sreg[j] + neta*m;
            g_chunkS[base + j] = sreg[j];
        }
    }
    float* Sgw = g_S + (size_t)(b*Hn + h)*4096;
    #pragma unroll
    for (int j = 0; j < 16; j++) Sgw[v*64 + kb + j] = sreg[j];
}

// ---------------- Polar Express (in-place on g_chunkS), one 64x64 matrix per block ----------------
// LDS-optimized: pitch-68 rows (16B aligned), ALL smem traffic as float4
// (conflict-free LDS.128/STS.128), explicit X^T copy so every matmul is
// row-major x row-major (no column-strided smem reads).  X^T is refreshed for
// free from mm3's register tile.  Numerics: Kahan for iters 0-1 (amplified
// ~124x/~30x downstream), plain 2-way split accumulators for iters 2-4.
#define PPITCH 68
#define PE_SMEM (4*64*PPITCH*4)   // 69,632 B -> 3 blocks/SM

// C[i0..+3][j0..+3] = sum_k A[i][k]*B[k][j], A,B row-major with pitch PPITCH.
template<bool KAHAN>
__device__ __forceinline__ void mmP(
    const float* __restrict__ A, const float* __restrict__ B,
    float o[4][4], int i0, int j0)
{
    float acc[4][4] = {};
    float aux[4][4] = {};   // Kahan compensation OR second split accumulator
    #pragma unroll 4
    for (int kb = 0; kb < 16; kb++) {
        const int k0 = kb*4;
        float4 a4[4], b4[4];
        #pragma unroll
        for (int r = 0; r < 4; r++)
            a4[r] = *(const float4*)(A + (i0+r)*PPITCH + k0);
        #pragma unroll
        for (int kk = 0; kk < 4; kk++)
            b4[kk] = *(const float4*)(B + (k0+kk)*PPITCH + j0);
        #pragma unroll
        for (int kk = 0; kk < 4; kk++) {
            float ar[4], br[4];
            br[0] = b4[kk].x; br[1] = b4[kk].y; br[2] = b4[kk].z; br[3] = b4[kk].w;
            #pragma unroll
            for (int r = 0; r < 4; r++) ar[r] = ((const float*)&a4[r])[kk];
            if (KAHAN) {
                #pragma unroll
                for (int r = 0; r < 4; r++)
                    #pragma unroll
                    for (int c = 0; c < 4; c++) {
                        float p = ar[r]*br[c];
                        float y = p - aux[r][c];
                        float s = acc[r][c] + y;
                        aux[r][c] = (s - acc[r][c]) - y;
                        acc[r][c] = s;
                    }
            } else {
                if (kk & 1) {
                    #pragma unroll
                    for (int r = 0; r < 4; r++)
                        #pragma unroll
                        for (int c = 0; c < 4; c++) aux[r][c] += ar[r]*br[c];
                } else {
                    #pragma unroll
                    for (int r = 0; r < 4; r++)
                        #pragma unroll
                        for (int c = 0; c < 4; c++) acc[r][c] += ar[r]*br[c];
                }
            }
        }
    }
    #pragma unroll
    for (int r = 0; r < 4; r++)
        #pragma unroll
        for (int c = 0; c < 4; c++)
            o[r][c] = KAHAN ? (acc[r][c] - aux[r][c]) : (acc[r][c] + aux[r][c]);
}

// One PE iteration.  Buffers: X (input), XT (X^T), S1 (scratch/out), S2 (scratch).
// Writes: Y -> S1, Y^T -> XT (skipped when !needT).  Caller swaps X<->S1 after.
template<bool KAHAN>
__device__ __forceinline__ void pe_iterP(
    float* X, float* XT, float* S1, float* S2,
    int i0, int j0, float ca, float cb, float cc, bool needT)
{
    float o[4][4];
    // S1 = X @ X^T   (row x row via XT)
    mmP<KAHAN>(X, XT, o, i0, j0);
    #pragma unroll
    for (int r = 0; r < 4; r++)
        *(float4*)(S1 + (i0+r)*PPITCH + j0) = make_float4(o[r][0], o[r][1], o[r][2], o[r][3]);
    __syncthreads();
    // S2 = cb*S1 + cc*(S1 @ S1)   (elementwise fold into the tile store)
    mmP<KAHAN>(S1, S1, o, i0, j0);
    #pragma unroll
    for (int r = 0; r < 4; r++) {
        float4 t = *(const float4*)(S1 + (i0+r)*PPITCH + j0);
        *(float4*)(S2 + (i0+r)*PPITCH + j0) =
            make_float4(cb*t.x + cc*o[r][0], cb*t.y + cc*o[r][1],
                        cb*t.z + cc*o[r][2], cb*t.w + cc*o[r][3]);
    }
    __syncthreads();
    // Y = ca*X + S2 @ X   -> S1, and Y^T -> XT (free from the register tile)
    mmP<KAHAN>(S2, X, o, i0, j0);
    #pragma unroll
    for (int r = 0; r < 4; r++) {
        float4 x = *(const float4*)(X + (i0+r)*PPITCH + j0);
        o[r][0] += ca*x.x; o[r][1] += ca*x.y; o[r][2] += ca*x.z; o[r][3] += ca*x.w;
        *(float4*)(S1 + (i0+r)*PPITCH + j0) = make_float4(o[r][0], o[r][1], o[r][2], o[r][3]);
    }
    if (needT) {
        #pragma unroll
        for (int c = 0; c < 4; c++)
            *(float4*)(XT + (j0+c)*PPITCH + i0) = make_float4(o[0][c], o[1][c], o[2][c], o[3][c]);
    }
    __syncthreads();
}

__global__ __launch_bounds__(256) void pe_kernel()
{
    extern __shared__ float sm[];
    float* X  = sm;
    float* XT = sm +   64*PPITCH;
    float* S1 = sm + 2*64*PPITCH;
    float* S2 = sm + 3*64*PPITCH;
    __shared__ float red[8];
    __shared__ float snorm;

    int tid = threadIdx.x;
    int tx = tid & 15, ty = tid >> 4;
    int i0 = ty*4, j0 = tx*4;
    float* gp = g_chunkS + (size_t)blockIdx.x * 4096;

    // load (vectorized) + Frobenius norm
    float lsum = 0.f;
    for (int i = tid; i < 1024; i += 256) {
        float4 f = ((const float4*)gp)[i];
        int row = i >> 4, c4 = (i & 15) * 4;
        *(float4*)(X + row*PPITCH + c4) = f;
        lsum += f.x*f.x + f.y*f.y + f.z*f.z + f.w*f.w;
    }
    #pragma unroll
    for (int m = 16; m >= 1; m >>= 1) lsum += __shfl_xor_sync(0xffffffffu, lsum, m);
    if ((tid & 31) == 0) red[tid >> 5] = lsum;
    __syncthreads();
    if (tid < 8) {
        float r2 = red[tid];
        r2 += __shfl_xor_sync(0xffu, r2, 4);
        r2 += __shfl_xor_sync(0xffu, r2, 2);
        r2 += __shfl_xor_sync(0xffu, r2, 1);
        if (tid == 0) snorm = 1.f/((sqrtf(r2) + 1e-7f)*1.01f);
    }
    __syncthreads();
    // scale in place + build X^T (per-thread 4x4 tile)
    {
        float sc = snorm;
        float t[4][4];
        #pragma unroll
        for (int r = 0; r < 4; r++) {
            float4 f = *(const float4*)(X + (i0+r)*PPITCH + j0);
            t[r][0] = f.x*sc; t[r][1] = f.y*sc; t[r][2] = f.z*sc; t[r][3] = f.w*sc;
            *(float4*)(X + (i0+r)*PPITCH + j0) = make_float4(t[r][0], t[r][1], t[r][2], t[r][3]);
        }
        #pragma unroll
        for (int c = 0; c < 4; c++)
            *(float4*)(XT + (j0+c)*PPITCH + i0) = make_float4(t[0][c], t[1][c], t[2][c], t[3][c]);
    }
    __syncthreads();

    // iters 0-1: Kahan (amplified ~124x / ~30x downstream)
    pe_iterP<true>(X, XT, S1, S2, i0, j0, PEC[0][0], PEC[0][1], PEC[0][2], true);
    { float* tmp = X; X = S1; S1 = tmp; }
    pe_iterP<true>(X, XT, S1, S2, i0, j0, PEC[1][0], PEC[1][1], PEC[1][2], true);
    { float* tmp = X; X = S1; S1 = tmp; }
    // iters 2-4: plain split-accumulator FMA
    #pragma unroll 1
    for (int it = 2; it < 5; it++) {
        pe_iterP<false>(X, XT, S1, S2, i0, j0, PEC[it][0], PEC[it][1], PEC[it][2], it < 4);
        float* tmp = X; X = S1; S1 = tmp;
    }

    // store result (vectorized)
    #pragma unroll
    for (int r = 0; r < 4; r++) {
        float4 f = *(const float4*)(X + (i0+r)*PPITCH + j0);
        *(float4*)(gp + (i0+r)*64 + j0) = f;
    }
}

// ---------------- per-chunk: memory scan M_t = a_t M_{t-1} + orth_t ; y_t = M_t q_t ----------------
__global__ __launch_bounds__(256) void memscan_kernel(const float* __restrict__ qbuf, int n)
{
    __shared__ float qs[64*64];
    __shared__ float al[64];
    int bx = blockIdx.x;
    int b = bx >> 4, h = bx & 15;
    int tid = threadIdx.x;
    int v = tid >> 2, p = tid & 3, kb = p*16;

    for (int idx = tid; idx < 4096; idx += 256) {
        int t = idx >> 6, d = idx & 63;
        qs[idx] = qbuf[(size_t)(b*Tlen + n*CSz + t)*Cdim + h*Dd + d];
    }
    if (tid < 64) al[tid] = g_alpha[(b*Tlen + n*CSz + tid)*Hn + h];

    float mreg[16];
    const float* Mg = g_M + (size_t)(b*Hn + h)*4096;
    #pragma unroll
    for (int j = 0; j < 16; j++) mreg[j] = Mg[v*64 + kb + j];
    __syncthreads();

    for (int t = 0; t < 64; t++) {
        float a = al[t];
        size_t base = ((((size_t)b*CSz + t)*Hn + h)*Dd + v)*Dd + kb;
        #pragma unroll
        for (int j = 0; j < 16; j++) mreg[j] = a*mreg[j] + g_chunkS[base + j];
        float pa = 0.f;
        #pragma unroll
        for (int j = 0; j < 16; j++) pa += mreg[j]*qs[t*64 + kb + j];
        pa += __shfl_xor_sync(0xffffffffu, pa, 1);
        pa += __shfl_xor_sync(0xffffffffu, pa, 2);
        if (p == 0)
            g_y[(size_t)(b*Tlen + n*CSz + t)*Cdim + h*Dd + v] = pa;
    }
    float* Mgw = g_M + (size_t)(b*Hn + h)*4096;
    #pragma unroll
    for (int j = 0; j < 16; j++) Mgw[v*64 + kb + j] = mreg[j];
}

// ---------------- launch ----------------
extern "C" void kernel_launch(void* const* d_in, const int* in_sizes, int n_in,
                              void* d_out, int out_size)
{
    const float* x   = (const float*)d_in[0];
    const float* Wq  = (const float*)d_in[1];
    const float* Wk  = (const float*)d_in[2];
    const float* Wv  = (const float*)d_in[3];
    const float* Wo  = (const float*)d_in[4];
    const float* cqw = (const float*)d_in[5];
    const float* cqb = (const float*)d_in[6];
    const float* ckw = (const float*)d_in[7];
    const float* ckb = (const float*)d_in[8];
    const float* cvw = (const float*)d_in[9];
    const float* cvb = (const float*)d_in[10];
    const float* Wa  = (const float*)d_in[11];
    const float* We  = (const float*)d_in[12];
    const float* Wt  = (const float*)d_in[13];
    const float* Wg  = (const float*)d_in[14];
    float* out = (float*)d_out;

    cudaFuncSetAttribute(chunk_err_kernel, cudaFuncAttributeMaxDynamicSharedMemorySize, CE_SMEM);
    cudaFuncSetAttribute(pe_kernel,        cudaFuncAttributeMaxDynamicSharedMemorySize, PE_SMEM);

    float *pxq, *pxk, *pxv, *pq, *pk, *pv, *py, *pyn;
    cudaGetSymbolAddress((void**)&pxq, g_xq);
    cudaGetSymbolAddress((void**)&pxk, g_xk);
    cudaGetSymbolAddress((void**)&pxv, g_xv);
    cudaGetSymbolAddress((void**)&pq,  g_q);
    cudaGetSymbolAddress((void**)&pk,  g_k);
    cudaGetSymbolAddress((void**)&pv,  g_v);
    cudaGetSymbolAddress((void**)&py,  g_y);
    cudaGetSymbolAddress((void**)&pyn, g_yn);

    zero_state_kernel<<<(Bsz*Hn*Dd*Dd + 255)/256, 256>>>();

    dim3 gq(Cdim/64, (Bsz*Tlen)/64, 3);
    sgemm_nt_qkv<<<gq, 256>>>(x, Wq, Wk, Wv, pxq, pxk, pxv, Bsz*Tlen, Cdim, Cdim);
    gates_kernel<<<Bsz*Tlen, 256>>>(x, Wa, We, Wt, Wg);
    conv_feat_kernel<<<Bsz*Tlen, 256>>>(pxq, cqw, cqb, pq, 1);
    conv_feat_kernel<<<Bsz*Tlen, 256>>>(pxk, ckw, ckb, pk, 1);
    conv_feat_kernel<<<Bsz*Tlen, 256>>>(pxv, cvw, cvb, pv, 0);

    for (int n = 0; n < NCH; n++) {
        chunk_err_kernel<<<Bsz*Hn, 256, CE_SMEM>>>(pk, pv, n);
        pe_kernel<<<Bsz*CSz*Hn, 256, PE_SMEM>>>();
        memscan_kernel<<<Bsz*Hn, 256>>>(pq, n);
    }

    ynorm_kernel<<<Bsz*Tlen, 256>>>(py, pyn);
    dim3 gg(Cdim/64, (Bsz*Tlen)/64);
    sgemm_nt<<<gg, 256>>>(pyn, Wo, out, Bsz*Tlen, Cdim, Cdim);
}